// round 5
// baseline (speedup 1.0000x reference)
#include <cuda_runtime.h>
#include <math.h>

// Problem constants: B=32, N=160, C=3, L=128
// SSIM: VALID 11x11 gaussian -> 150x150 output
// STFT: f=12, s=4 -> p=38 patches/dim, bins u,v in 1..5, weight u*v/25

#define SSIM_BLOCKS (5*5*96)   // 25 tiles x (32 b * 3 c) = 2400
#define STFT_BLOCKS (38*32)    // patch rows x batch = 1216
#define TOTAL_BLOCKS (SSIM_BLOCKS + STFT_BLOCKS)

__device__ float g_ssim[SSIM_BLOCKS];
__device__ float g_stft[STFT_BLOCKS];
__device__ unsigned int g_count = 0;   // completion counter (reset by last block)

// gaussian weights (normalized), compile-time immediates
__device__ __forceinline__ constexpr float GNW(int k) {
    constexpr float g[11] = {0.00102838f, 0.00759887f, 0.03600077f, 0.10936069f,
                             0.21300553f, 0.26601172f, 0.21300553f, 0.10936069f,
                             0.03600077f, 0.00759887f, 0.00102838f};
    return g[k];
}

__device__ __forceinline__ constexpr float cw12f(int k) {
    constexpr float t[12] = { 1.f, 0.86602540378f, 0.5f, 0.f, -0.5f, -0.86602540378f,
                             -1.f,-0.86602540378f,-0.5f, 0.f,  0.5f,  0.86602540378f};
    return t[k];
}
__device__ __forceinline__ constexpr float sw12f(int k) {
    constexpr float t[12] = { 0.f, 0.5f, 0.86602540378f, 1.f, 0.86602540378f, 0.5f,
                              0.f,-0.5f,-0.86602540378f,-1.f,-0.86602540378f,-0.5f};
    return t[k];
}

// 12-point real-input DFT, bins u=1..5, hand-factored
__device__ __forceinline__ void dft12_5(const float* __restrict__ v,
                                        float* __restrict__ hr,
                                        float* __restrict__ hi)
{
    const float S3 = 0.86602540378f;
    float A1 = v[1]-v[5]-v[7]+v[11];
    float B1 = v[2]-v[4]-v[8]+v[10];
    float D1 = v[0]-v[6];
    float A2 = v[1]+v[5]-v[7]-v[11];
    float B2 = v[2]+v[4]-v[8]-v[10];
    float D2 = v[3]-v[9];
    float t1 = S3*A1, t2 = 0.5f*B1;
    float s1 = 0.5f*A2, s2 = S3*B2;
    hr[0] = D1 + t1 + t2;            hi[0] = -(s1 + s2 + D2);   // u=1
    hr[4] = D1 - t1 + t2;            hi[4] = -(s1 - s2 + D2);   // u=5
    float p0 = v[0]+v[6], p3 = v[3]+v[9];
    float q1 = v[1]+v[7], q2 = v[2]+v[8], q4 = v[4]+v[10], q5 = v[5]+v[11];
    hr[1] = (p0 - p3) + 0.5f*((q1+q5) - (q2+q4));               // u=2
    hi[1] = -S3*((q1+q2) - (q4+q5));
    hr[2] = (v[0]+v[4]+v[8]) - (v[2]+v[6]+v[10]);               // u=3
    hi[2] = (v[3]+v[7]+v[11]) - (v[1]+v[5]+v[9]);
    float E0 = p0+p3, E1 = q1+q4, E2 = q2+q5;
    hr[3] = E0 - 0.5f*(E1+E2);                                  // u=4
    hi[3] = -S3*(E1-E2);
}

__device__ __forceinline__ float fast_atan2f(float y, float x) {
    float ax = fabsf(x), ay = fabsf(y);
    float mx = fmaxf(ax, ay), mn = fminf(ax, ay);
    float t = __fdividef(mn, mx);
    float s = t*t;
    float p =             -0.01172120f;
    p = fmaf(p, s,         0.05265332f);
    p = fmaf(p, s,        -0.11643287f);
    p = fmaf(p, s,         0.19354346f);
    p = fmaf(p, s,        -0.33262347f);
    p = fmaf(p, s,         0.99997726f);
    float r = p * t;
    if (ay > ax)  r = 1.57079632679f - r;
    if (x < 0.f)  r = 3.14159265359f - r;
    return copysignf(r, y);
}

// ---------------------------------------------------------------------------
// Fused compute kernel: bid < STFT_BLOCKS -> stft work; else ssim work.
// Last block to finish performs the final fixed-order fp64 reduction
// (threadfence-reduction pattern; deterministic summation order).
// ---------------------------------------------------------------------------
union SmemU {
    float  red[256];                      // aliases the fronts (sync-guarded)
    double dred[256];                     // final-reduction buffer (last block)
    struct {
        ulonglong2 H[5][540];             // [u][swizzled col] = {reI,imI,reO,imO}
    } stft;
    struct {
        float2 sxy[42][45];               // (x,y) pixel pairs
        float2 hA[42][33];                // (hx, hy)
        float2 hB[42][33];                // (h_{xx+yy}, h_xy)
    } ssim;
};

__global__ void __launch_bounds__(256, 4) fused_kernel(const float* __restrict__ xin,
                                                       const float* __restrict__ xout,
                                                       const float* __restrict__ mean,
                                                       const float* __restrict__ logvar,
                                                       float* __restrict__ out)
{
    __shared__ SmemU S;
    __shared__ bool s_isLast;
    const int tid = threadIdx.x;
    const int bid = blockIdx.x;

    if (bid < STFT_BLOCKS) {
        // =================== STFT path ===================
        const int b = bid / 38;
        const int prow = bid - b * 38;    // image rows prow*4 .. prow*4+11

        const float* pin  = xin  + ((long)b * 160 + (long)prow * 4) * 480;
        const float* pout = xout + ((long)b * 160 + (long)prow * 4) * 480;

        // Phase A: column DFTs straight from gmem (coalesced across lanes)
        for (int e = tid; e < 480; e += 256) {
            float vi[12], vo[12];
            #pragma unroll
            for (int y = 0; y < 12; y++) {
                vi[y] = pin [y*480 + e];
                vo[y] = pout[y*480 + e];
            }
            float hir[5], hii[5], hor[5], hoi[5];
            dft12_5(vi, hir, hii);
            dft12_5(vo, hor, hoi);
            const int es = e + (e >> 3);  // bank swizzle
            #pragma unroll
            for (int u = 0; u < 5; u++) {
                float4 f = make_float4(hir[u], hii[u], hor[u], hoi[u]);
                S.stft.H[u][es] = *reinterpret_cast<ulonglong2*>(&f);
            }
        }
        __syncthreads();

        // Phase B: 570 items = 38 patches x 3 ch x 5 u
        float acc = 0.f;
        for (int id = tid; id < 570; id += 256) {
            const int u = id / 114;       // 0..4  (bin u+1)
            const int m = id - u*114;     // 0..113 = j*3 + c
            const int cch = m % 3;
            const int ebase = 4*m - 3*cch;  // = 12j + c

            float Fir[5], Fii[5], For[5], Foi[5];
            #pragma unroll
            for (int v = 0; v < 5; v++) { Fir[v]=0.f; Fii[v]=0.f; For[v]=0.f; Foi[v]=0.f; }

            #pragma unroll
            for (int x = 0; x < 12; x++) {
                const int e = ebase + 3*x;
                const int es = e + (e >> 3);
                ulonglong2 hraw = S.stft.H[u][es];
                float4 h = *reinterpret_cast<float4*>(&hraw);
                #pragma unroll
                for (int v = 1; v <= 5; v++) {
                    const int k = (v*x) % 12;
                    const float c_ = cw12f(k), s_ = sw12f(k);
                    const int vi = v - 1;
                    if (s_ == 0.f) {
                        if (c_ > 0.f) { Fir[vi]+=h.x; Fii[vi]+=h.y; For[vi]+=h.z; Foi[vi]+=h.w; }
                        else          { Fir[vi]-=h.x; Fii[vi]-=h.y; For[vi]-=h.z; Foi[vi]-=h.w; }
                    } else if (c_ == 0.f) {
                        if (s_ > 0.f) { Fir[vi]+=h.y; Fii[vi]-=h.x; For[vi]+=h.w; Foi[vi]-=h.z; }
                        else          { Fir[vi]-=h.y; Fii[vi]+=h.x; For[vi]-=h.w; Foi[vi]+=h.z; }
                    } else {
                        Fir[vi] = fmaf(h.x,  c_, fmaf(h.y,  s_, Fir[vi]));
                        Fii[vi] = fmaf(h.y,  c_, fmaf(h.x, -s_, Fii[vi]));
                        For[vi] = fmaf(h.z,  c_, fmaf(h.w,  s_, For[vi]));
                        Foi[vi] = fmaf(h.w,  c_, fmaf(h.z, -s_, Foi[vi]));
                    }
                }
            }

            const float wu = (float)(u + 1) * (1.f / 25.f);
            #pragma unroll
            for (int v = 1; v <= 5; v++) {
                const int vi = v - 1;
                float angi = fast_atan2f(Fii[vi], Fir[vi] + 1e-8f);
                float ango = fast_atan2f(Foi[vi], For[vi] + 1e-8f);
                float m2i = fmaf(Fir[vi], Fir[vi], Fii[vi]*Fii[vi]);
                float m2o = fmaf(For[vi], For[vi], Foi[vi]*Foi[vi]);
                float magi = m2i * __frsqrt_rn(fmaxf(m2i, 1e-30f));
                float mago = m2o * __frsqrt_rn(fmaxf(m2o, 1e-30f));
                acc = fmaf((float)v * wu, fabsf(ango - angi) + fabsf(mago - magi), acc);
            }
        }

        __syncthreads();                  // red aliases H: all reads must finish
        S.red[tid] = acc;
        __syncthreads();
        #pragma unroll
        for (int s = 128; s > 0; s >>= 1) {
            if (tid < s) S.red[tid] += S.red[tid + s];
            __syncthreads();
        }
        if (tid == 0)
            g_stft[bid] = S.red[0];

    } else {
        // =================== SSIM path ===================
        const int idx = bid - STFT_BLOCKS;
        const int bz = idx / 25;          // b*3 + c
        const int r25 = idx - bz*25;
        const int by = r25 / 5, bx = r25 - by*5;
        const int c  = bz % 3, b = bz / 3;
        const int ox = bx * 32, oy = by * 32;

        const float* pin  = xin  + (size_t)b * (160*160*3) + c;
        const float* pout = xout + (size_t)b * (160*160*3) + c;

        // load 42x42 input tile (halo), zero-pad OOB (those outputs masked)
        for (int i = tid; i < 42*42; i += 256) {
            int r = i / 42, cc = i - r*42;
            int gr = oy + r, gc = ox + cc;
            float vx = 0.f, vy = 0.f;
            if (gr < 160 && gc < 160) {
                size_t off = ((size_t)gr*160 + gc) * 3;
                vx = pin[off]; vy = pout[off];
            }
            S.ssim.sxy[r][cc] = make_float2(vx, vy);
        }
        __syncthreads();

        // horizontal pass: 42 rows x 8 groups of 4 cols, k-outer
        for (int i = tid; i < 42*8; i += 256) {
            int r = i >> 3, c0 = (i & 7) * 4;
            float2 A[4], Bv[4];
            #pragma unroll
            for (int g = 0; g < 4; g++) { A[g] = make_float2(0.f,0.f); Bv[g] = make_float2(0.f,0.f); }
            #pragma unroll
            for (int k = 0; k < 14; k++) {
                float2 xy = S.ssim.sxy[r][c0 + k];
                float ss = fmaf(xy.y, xy.y, xy.x*xy.x);
                float ad = xy.x * xy.y;
                #pragma unroll
                for (int g = 0; g < 4; g++) {
                    const int kk = k - g;
                    if (kk >= 0 && kk < 11) {
                        const float w = GNW(kk);
                        A[g].x  = fmaf(w, xy.x, A[g].x);
                        A[g].y  = fmaf(w, xy.y, A[g].y);
                        Bv[g].x = fmaf(w, ss,   Bv[g].x);
                        Bv[g].y = fmaf(w, ad,   Bv[g].y);
                    }
                }
            }
            #pragma unroll
            for (int g = 0; g < 4; g++) {
                S.ssim.hA[r][c0 + g] = A[g];
                S.ssim.hB[r][c0 + g] = Bv[g];
            }
        }
        __syncthreads();

        // vertical pass: 32 cols x 8 row-groups, 4 outputs/thread, k-outer
        const int tx = tid & 31, ty = tid >> 5;
        const int rb = ty * 4;

        float2 aA[4], aB[4];
        #pragma unroll
        for (int g = 0; g < 4; g++) { aA[g] = make_float2(0.f,0.f); aB[g] = make_float2(0.f,0.f); }

        #pragma unroll
        for (int k = 0; k < 14; k++) {
            float2 tA = S.ssim.hA[rb + k][tx];
            float2 tB = S.ssim.hB[rb + k][tx];
            #pragma unroll
            for (int g = 0; g < 4; g++) {
                const int kk = k - g;
                if (kk >= 0 && kk < 11) {
                    const float w = GNW(kk);
                    aA[g].x = fmaf(w, tA.x, aA[g].x);
                    aA[g].y = fmaf(w, tA.y, aA[g].y);
                    aB[g].x = fmaf(w, tB.x, aB[g].x);
                    aB[g].y = fmaf(w, tB.y, aB[g].y);
                }
            }
        }

        float val = 0.f;
        const int gx = ox + tx;
        #pragma unroll
        for (int g = 0; g < 4; g++) {
            int gy = oy + rb + g;
            if (gx < 150 && gy < 150) {
                const float C1 = 1e-4f, C2 = 9e-4f;
                float mx = aA[g].x, my = aA[g].y;
                float vsum = aB[g].x - mx*mx - my*my;   // var_x + var_y
                float cov  = aB[g].y - mx*my;
                float lum = __fdividef(2.f*mx*my + C1, mx*mx + my*my + C1);
                float cs  = __fdividef(2.f*cov + C2, vsum + C2);
                val = fmaf(lum, cs, val);
            }
        }

        S.red[tid] = val;
        __syncthreads();
        #pragma unroll
        for (int s = 128; s > 0; s >>= 1) {
            if (tid < s) S.red[tid] += S.red[tid + s];
            __syncthreads();
        }
        if (tid == 0)
            g_ssim[idx] = S.red[0];
    }

    // =================== last-block final reduction ===================
    __threadfence();                      // publish g_ssim/g_stft write
    if (tid == 0) {
        unsigned int old = atomicAdd(&g_count, 1u);
        s_isLast = (old == TOTAL_BLOCKS - 1);
    }
    __syncthreads();

    if (s_isLast) {
        const double K_KLD  = -0.5 / 32.0;
        const double K_SSIM = 1.0 / (32.0 * 150.0 * 150.0 * 3.0);
        const double K_STFT = 1e-4 / 32.0;

        double acc = 0.0;
        for (int i = tid; i < 32*128; i += 256) {
            float lv = logvar[i], m = mean[i];
            acc += (double)(1.0f + lv - expf(lv) - m*m) * K_KLD;
        }
        for (int i = tid; i < SSIM_BLOCKS; i += 256)
            acc += (double)__ldcg(&g_ssim[i]) * K_SSIM;
        for (int i = tid; i < STFT_BLOCKS; i += 256)
            acc += (double)__ldcg(&g_stft[i]) * K_STFT;

        __syncthreads();                  // smem reuse guard
        S.dred[tid] = acc;
        __syncthreads();
        #pragma unroll
        for (int s = 128; s > 0; s >>= 1) {
            if (tid < s) S.dred[tid] += S.dred[tid + s];
            __syncthreads();
        }
        if (tid == 0) {
            out[0] = (float)S.dred[0];
            g_count = 0;                  // reset for next graph replay
        }
    }
}

// ---------------------------------------------------------------------------
extern "C" void kernel_launch(void* const* d_in, const int* in_sizes, int n_in,
                              void* d_out, int out_size)
{
    const float* mean   = (const float*)d_in[0];
    const float* logvar = (const float*)d_in[1];
    const float* xin    = (const float*)d_in[2];
    const float* xout   = (const float*)d_in[3];
    float* out = (float*)d_out;

    fused_kernel<<<TOTAL_BLOCKS, 256>>>(xin, xout, mean, logvar, out);
}